// round 10
// baseline (speedup 1.0000x reference)
#include <cuda_runtime.h>
#include <math.h>

// ---------------------------------------------------------------------------
// MomentPredictor: 16-step autoregressive rollout of a 2-layer causal
// transformer (B=512, D=512, H=8, FF=2048). Implemented as exact incremental
// decoding with a KV cache (causal mask + per-token LN make prefix states
// step-invariant). fp32 throughout for the 1e-3 tolerance.
// ---------------------------------------------------------------------------

#define NB   512   // batch
#define NT   16    // time steps
#define NDIN 7
#define ND   512   // model dim
#define NL   2     // layers
#define NH   8     // heads
#define NHD  64    // head dim
#define NFF  2048

// ---- scratch (device globals: no runtime allocation allowed) ----
__device__ float g_h  [NB * ND];    // current hidden
__device__ float g_h1 [NB * ND];    // post-LN1 hidden
__device__ float g_tmp[NB * ND];    // pre-LN accumulator
__device__ float g_q  [NB * ND];    // Q for current token
__device__ float g_att[NB * ND];    // attention output
__device__ float g_ff [NB * NFF];   // FF1 activations
__device__ float g_kc [NL * NB * NH * NT * NHD];  // K cache
__device__ float g_vc [NL * NB * NH * NT * NHD];  // V cache
__device__ float g_y  [NB * 3];     // feedback prediction

// ---------------------------------------------------------------------------
// embed: h[b,d] = x_t[b,:] @ ip_w + ip_b + PE(t, d)
// channels 4..6 of x_t come from g_y for t>0 (autoregressive feedback)
// ---------------------------------------------------------------------------
__global__ void embed_k(const float* __restrict__ x,
                        const float* __restrict__ ipw,
                        const float* __restrict__ ipb, int t) {
    int b = blockIdx.x;
    int d = threadIdx.x;            // 512 threads
    float xin[NDIN];
    const float* xr = x + (b * NT + t) * NDIN;
#pragma unroll
    for (int k = 0; k < NDIN; k++) xin[k] = xr[k];
    if (t > 0) {
        xin[4] = g_y[b * 3 + 0];
        xin[5] = g_y[b * 3 + 1];
        xin[6] = g_y[b * 3 + 2];
    }
    float acc = ipb[d];
#pragma unroll
    for (int k = 0; k < NDIN; k++) acc = fmaf(xin[k], ipw[k * ND + d], acc);
    // positional encoding: pe[t, 2i] = sin(t*div_i), pe[t, 2i+1] = cos(t*div_i)
    int   i2  = (d >> 1) << 1;
    float div = expf(-(float)i2 * (9.210340371976184f / 512.0f)); // ln(1e4)/D
    float ang = (float)t * div;
    acc += (d & 1) ? cosf(ang) : sinf(ang);
    g_h[b * ND + d] = acc;
}

// ---------------------------------------------------------------------------
// sgemm64: 64x64 tile, BK=16, 256 threads, 4x4 per thread (float4 smem reads)
// MODE 0: QKV — A=g_h, N=1536; epilogue scatters Q / K-cache / V-cache
// MODE 1: FF1 — A=g_h1, N=2048; epilogue bias + relu -> g_ff
// ---------------------------------------------------------------------------
template <int MODE>
__global__ void sgemm64_k(const float* __restrict__ W,
                          const float* __restrict__ bias,
                          int N, int K, int l, int t) {
    __shared__ __align__(16) float As[16][64];
    __shared__ __align__(16) float Bs[16][64];

    const float* A = (MODE == 0) ? g_h : g_h1;
    int tid = threadIdx.x;
    int tx = tid & 15, ty = tid >> 4;
    int bm = blockIdx.y << 6, bn = blockIdx.x << 6;

    int arow = tid >> 2,  ac4 = (tid & 3) << 2;   // A tile: 64 rows x 16 k
    int brow = tid >> 4,  bc4 = (tid & 15) << 2;  // B tile: 16 k x 64 cols

    const float* Aptr = A + (bm + arow) * K + ac4;
    const float* Wptr = W + brow * N + bn + bc4;

    float acc[4][4];
#pragma unroll
    for (int i = 0; i < 4; i++)
#pragma unroll
        for (int j = 0; j < 4; j++) acc[i][j] = 0.f;

    for (int k0 = 0; k0 < K; k0 += 16) {
        float4 av = *(const float4*)(Aptr + k0);
        As[ac4 + 0][arow] = av.x;
        As[ac4 + 1][arow] = av.y;
        As[ac4 + 2][arow] = av.z;
        As[ac4 + 3][arow] = av.w;
        float4 bv = *(const float4*)(Wptr + (size_t)k0 * N);
        *(float4*)&Bs[brow][bc4] = bv;
        __syncthreads();
#pragma unroll
        for (int k = 0; k < 16; k++) {
            float4 a = *(const float4*)&As[k][ty << 2];
            float4 b = *(const float4*)&Bs[k][tx << 2];
            float ar[4] = {a.x, a.y, a.z, a.w};
            float br[4] = {b.x, b.y, b.z, b.w};
#pragma unroll
            for (int i = 0; i < 4; i++)
#pragma unroll
                for (int j = 0; j < 4; j++)
                    acc[i][j] = fmaf(ar[i], br[j], acc[i][j]);
        }
        __syncthreads();
    }

#pragma unroll
    for (int i = 0; i < 4; i++) {
        int m = bm + (ty << 2) + i;
#pragma unroll
        for (int j = 0; j < 4; j++) {
            int col = bn + (tx << 2) + j;
            float v = acc[i][j] + bias[col];
            if (MODE == 1) {
                g_ff[m * NFF + col] = fmaxf(v, 0.f);
            } else {
                if (col < ND) {
                    g_q[m * ND + col] = v;
                } else if (col < 2 * ND) {
                    int c = col - ND;
                    g_kc[(size_t)l * (NB * NH * NT * NHD) +
                         (size_t)((m * NH + (c >> 6)) * NT + t) * NHD + (c & 63)] = v;
                } else {
                    int c = col - 2 * ND;
                    g_vc[(size_t)l * (NB * NH * NT * NHD) +
                         (size_t)((m * NH + (c >> 6)) * NT + t) * NHD + (c & 63)] = v;
                }
            }
        }
    }
}

// ---------------------------------------------------------------------------
// sgemm32: 32x32 tile, BK=16, 64 threads, 4x4 per thread. N=512 output so
// grid = 256 blocks (covers all 148 SMs, unlike a 64-block 64x64 grid).
// mode 0: out-proj  (A=g_att, resid=g_h)   -> g_tmp
// mode 1: FF2       (A=g_ff,  resid=g_h1)  -> g_tmp
// ---------------------------------------------------------------------------
__global__ void sgemm32_k(const float* __restrict__ W,
                          const float* __restrict__ bias,
                          int K, int mode) {
    __shared__ __align__(16) float As[16][32];
    __shared__ __align__(16) float Bs[16][32];

    const float* A = mode ? g_ff : g_att;
    const float* R = mode ? g_h1 : g_h;
    const int N = ND;
    int tid = threadIdx.x;                 // 64 threads
    int tx = tid & 7, ty = tid >> 3;
    int bm = blockIdx.y << 5, bn = blockIdx.x << 5;

    float acc[4][4];
#pragma unroll
    for (int i = 0; i < 4; i++)
#pragma unroll
        for (int j = 0; j < 4; j++) acc[i][j] = 0.f;

    for (int k0 = 0; k0 < K; k0 += 16) {
#pragma unroll
        for (int r = 0; r < 2; r++) {
            int idx = tid + (r << 6);
            int row = idx >> 2, c4 = (idx & 3) << 2;           // A: 32x16
            float4 av = *(const float4*)&A[(size_t)(bm + row) * K + k0 + c4];
            As[c4 + 0][row] = av.x;
            As[c4 + 1][row] = av.y;
            As[c4 + 2][row] = av.z;
            As[c4 + 3][row] = av.w;
            int br = idx >> 3, bc = (idx & 7) << 2;            // B: 16x32
            float4 bv = *(const float4*)&W[(size_t)(k0 + br) * N + bn + bc];
            *(float4*)&Bs[br][bc] = bv;
        }
        __syncthreads();
#pragma unroll
        for (int k = 0; k < 16; k++) {
            float4 a = *(const float4*)&As[k][ty << 2];
            float4 b = *(const float4*)&Bs[k][tx << 2];
            float ar[4] = {a.x, a.y, a.z, a.w};
            float br[4] = {b.x, b.y, b.z, b.w};
#pragma unroll
            for (int i = 0; i < 4; i++)
#pragma unroll
                for (int j = 0; j < 4; j++)
                    acc[i][j] = fmaf(ar[i], br[j], acc[i][j]);
        }
        __syncthreads();
    }

#pragma unroll
    for (int i = 0; i < 4; i++) {
        int m = bm + (ty << 2) + i;
#pragma unroll
        for (int j = 0; j < 4; j++) {
            int col = bn + (tx << 2) + j;
            g_tmp[m * N + col] = acc[i][j] + bias[col] + R[m * N + col];
        }
    }
}

// ---------------------------------------------------------------------------
// LayerNorm over g_tmp rows -> (outsel ? g_h : g_h1)
// ---------------------------------------------------------------------------
__global__ void ln_k(const float* __restrict__ gam,
                     const float* __restrict__ bet, int outsel) {
    int b = blockIdx.x, tid = threadIdx.x;   // 256 threads, 2 elems each
    float v0 = g_tmp[b * ND + tid];
    float v1 = g_tmp[b * ND + tid + 256];
    __shared__ float sh[8], sh2[8];

    float s = v0 + v1;
#pragma unroll
    for (int o = 16; o; o >>= 1) s += __shfl_xor_sync(0xffffffffu, s, o);
    if ((tid & 31) == 0) sh[tid >> 5] = s;
    __syncthreads();
    float tot = 0.f;
#pragma unroll
    for (int i = 0; i < 8; i++) tot += sh[i];
    float mean = tot * (1.0f / 512.0f);

    float d0 = v0 - mean, d1 = v1 - mean;
    float q = d0 * d0 + d1 * d1;
#pragma unroll
    for (int o = 16; o; o >>= 1) q += __shfl_xor_sync(0xffffffffu, q, o);
    if ((tid & 31) == 0) sh2[tid >> 5] = q;
    __syncthreads();
    float vtot = 0.f;
#pragma unroll
    for (int i = 0; i < 8; i++) vtot += sh2[i];
    float inv = rsqrtf(vtot * (1.0f / 512.0f) + 1e-5f);

    float* out = outsel ? g_h : g_h1;
    out[b * ND + tid]       = d0 * inv * gam[tid]       + bet[tid];
    out[b * ND + tid + 256] = d1 * inv * gam[tid + 256] + bet[tid + 256];
}

// ---------------------------------------------------------------------------
// attention: one warp per (b, h); lane owns head-dims (lane, lane+32).
// Q of new token vs K/V cache positions 0..t. Writes g_att.
// ---------------------------------------------------------------------------
__global__ void attn_k(int t, int l) {
    int wg   = (blockIdx.x << 2) + (threadIdx.x >> 5);  // global warp id
    int lane = threadIdx.x & 31;
    int b = wg >> 3, h = wg & 7;

    const float* qp = g_q + b * ND + h * NHD;
    float q0 = qp[lane], q1 = qp[lane + 32];

    const float* kb = g_kc + (size_t)l * (NB * NH * NT * NHD) + (size_t)(b * NH + h) * NT * NHD;
    const float* vb = g_vc + (size_t)l * (NB * NH * NT * NHD) + (size_t)(b * NH + h) * NT * NHD;

    float sc[NT];
#pragma unroll
    for (int p = 0; p < NT; p++) {
        float s = -1e30f;
        if (p <= t) {
            s = q0 * kb[p * NHD + lane] + q1 * kb[p * NHD + lane + 32];
#pragma unroll
            for (int o = 16; o; o >>= 1) s += __shfl_xor_sync(0xffffffffu, s, o);
            s *= 0.125f;   // 1/sqrt(64)
        }
        sc[p] = s;
    }
    float mx = -1e30f;
#pragma unroll
    for (int p = 0; p < NT; p++) mx = fmaxf(mx, sc[p]);
    float sum = 0.f;
#pragma unroll
    for (int p = 0; p < NT; p++) {
        float e = expf(sc[p] - mx);   // p>t: exp(-1e30) == 0
        sc[p] = e;
        sum += e;
    }
    float invs = 1.0f / sum;
    float o0 = 0.f, o1 = 0.f;
#pragma unroll
    for (int p = 0; p < NT; p++) {
        if (p <= t) {
            float a = sc[p] * invs;
            o0 = fmaf(a, vb[p * NHD + lane],      o0);
            o1 = fmaf(a, vb[p * NHD + lane + 32], o1);
        }
    }
    g_att[b * ND + h * NHD + lane]      = o0;
    g_att[b * ND + h * NHD + lane + 32] = o1;
}

// ---------------------------------------------------------------------------
// head: y[b,c] = g_h[b,:] @ head_w[:,c] + head_b[c]; one warp per output col.
// Writes d_out[b, t, c] and the feedback buffer g_y.
// ---------------------------------------------------------------------------
__global__ void head_k(const float* __restrict__ hw,
                       const float* __restrict__ hb,
                       float* __restrict__ out, int t) {
    int b = blockIdx.x;
    int w = threadIdx.x >> 5;        // 0..2 (96 threads)
    int lane = threadIdx.x & 31;
    float acc = 0.f;
#pragma unroll
    for (int i = 0; i < 16; i++) {
        int d = lane + (i << 5);
        acc = fmaf(g_h[b * ND + d], hw[d * 3 + w], acc);
    }
#pragma unroll
    for (int o = 16; o; o >>= 1) acc += __shfl_xor_sync(0xffffffffu, acc, o);
    if (lane == 0) {
        float v = acc + hb[w];
        out[(b * NT + t) * 3 + w] = v;
        g_y[b * 3 + w] = v;
    }
}

// ---------------------------------------------------------------------------
extern "C" void kernel_launch(void* const* d_in, const int* in_sizes, int n_in,
                              void* d_out, int out_size) {
    const float* x    = (const float*)d_in[0];
    const float* ipw  = (const float*)d_in[1];
    const float* ipb  = (const float*)d_in[2];
    const float* qkvw = (const float*)d_in[3];
    const float* qkvb = (const float*)d_in[4];
    const float* outw = (const float*)d_in[5];
    const float* outb = (const float*)d_in[6];
    const float* ln1s = (const float*)d_in[7];
    const float* ln1b = (const float*)d_in[8];
    const float* ffw1 = (const float*)d_in[9];
    const float* ffb1 = (const float*)d_in[10];
    const float* ffw2 = (const float*)d_in[11];
    const float* ffb2 = (const float*)d_in[12];
    const float* ln2s = (const float*)d_in[13];
    const float* ln2b = (const float*)d_in[14];
    const float* hw   = (const float*)d_in[15];
    const float* hb   = (const float*)d_in[16];
    float* out = (float*)d_out;

    (void)in_sizes; (void)n_in; (void)out_size;

    for (int t = 0; t < NT; t++) {
        embed_k<<<NB, ND>>>(x, ipw, ipb, t);
        for (int l = 0; l < NL; l++) {
            // QKV: 512 x 1536, K=512 -> Q buffer + KV caches at position t
            sgemm64_k<0><<<dim3(3 * ND / 64, NB / 64), 256>>>(
                qkvw + (size_t)l * ND * 3 * ND, qkvb + l * 3 * ND, 3 * ND, ND, l, t);
            // attention over cached positions 0..t
            attn_k<<<NB * NH / 4, 128>>>(t, l);
            // out-proj + bias + residual -> g_tmp
            sgemm32_k<<<dim3(ND / 32, NB / 32), 64>>>(
                outw + (size_t)l * ND * ND, outb + l * ND, ND, 0);
            ln_k<<<NB, 256>>>(ln1s + l * ND, ln1b + l * ND, 0);   // -> g_h1
            // FF1: 512 x 2048 + relu
            sgemm64_k<1><<<dim3(NFF / 64, NB / 64), 256>>>(
                ffw1 + (size_t)l * ND * NFF, ffb1 + l * NFF, NFF, ND, l, t);
            // FF2: K=2048 + bias + residual -> g_tmp
            sgemm32_k<<<dim3(ND / 32, NB / 32), 64>>>(
                ffw2 + (size_t)l * NFF * ND, ffb2 + l * ND, NFF, 1);
            ln_k<<<NB, 256>>>(ln2s + l * ND, ln2b + l * ND, 1);   // -> g_h
        }
        head_k<<<NB, 96>>>(hw, hb, out, t);
    }
}